// round 15
// baseline (speedup 1.0000x reference)
#include <cuda_runtime.h>
#include <cuda_fp16.h>
#include <cstdint>
#include <math.h>

#define E_EDGES 500000
#define NOLD    100000
#define NNEW    100000
#define NENT    100000
#define NREL    500
#define D_EMB   100
#define H_DIM   128
#define G3H     384

// ---------------- scratch (device globals; no allocation allowed) ----------------
__device__ __align__(16) __half   g_ns16[NOLD * H_DIM];        // node_emb @ Ws^T (fp16)
__device__ __align__(16) __half   g_node_hh[NOLD * G3H];       // node_emb @ W_hh^T (fp16)
__device__ __align__(16) __half   g_ent_proj[NENT * G3H];      // ent_table @ W_ih[:, :100]^T (fp16)
__device__ __align__(16) float    g_rel_wr[NREL * H_DIM];
__device__ __align__(16) float    g_rel_wqr[NREL * H_DIM];     // includes +bqr folded in
__device__ __align__(16) float    g_rel_gru[NREL * G3H];
__device__ float                  g_denom[NNEW];
__device__ __align__(16) float    g_agg[NNEW * H_DIM];         // unnormalized: sum ex*msg
__device__ __align__(16) __half   g_agg16[NNEW * H_DIM];
// fp16 planes (zero-padded to K=128)
__device__ __align__(16) __half g_A16[NOLD * 128];     // node_emb fp16 (GEMM A + hs gather source)
__device__ __align__(16) __half g_E16[NENT * 128];     // ent_table fp16
__device__ __align__(16) __half g_Ws16[128 * 128];
__device__ __align__(16) __half g_Whh16[G3H * 128];
__device__ __align__(16) __half g_Wih16[G3H * 128];
__device__ __align__(16) __half g_Wh16[128 * 128];

// ---------------- helpers ----------------
__device__ __forceinline__ uint32_t smem_u32(const void* p) {
    uint32_t a;
    asm("{ .reg .u64 t; cvta.to.shared.u64 t, %1; cvt.u32.u64 %0, t; }" : "=r"(a) : "l"(p));
    return a;
}
__device__ __forceinline__ void ldm_x4(uint32_t* r, uint32_t addr) {
    asm volatile("ldmatrix.sync.aligned.m8n8.x4.shared.b16 {%0,%1,%2,%3}, [%4];"
                 : "=r"(r[0]), "=r"(r[1]), "=r"(r[2]), "=r"(r[3]) : "r"(addr));
}
__device__ __forceinline__ void mma_f16(float* d, const uint32_t* a, uint32_t b0, uint32_t b1) {
    asm volatile(
        "mma.sync.aligned.m16n8k16.row.col.f32.f16.f16.f32 "
        "{%0,%1,%2,%3}, {%4,%5,%6,%7}, {%8,%9}, {%0,%1,%2,%3};"
        : "+f"(d[0]), "+f"(d[1]), "+f"(d[2]), "+f"(d[3])
        : "r"(a[0]), "r"(a[1]), "r"(a[2]), "r"(a[3]), "r"(b0), "r"(b1));
}
__device__ __forceinline__ uint32_t swz(int r, int u) {
    return (uint32_t)(r * 256) + ((uint32_t)((u & 8) | ((u & 7) ^ (r & 7))) << 4);
}
__device__ __forceinline__ float4 ld_half4(const __half* p) {
    uint2 u = *reinterpret_cast<const uint2*>(p);
    __half2 h01 = *reinterpret_cast<__half2*>(&u.x);
    __half2 h23 = *reinterpret_cast<__half2*>(&u.y);
    float2 f01 = __half22float2(h01);
    float2 f23 = __half22float2(h23);
    return make_float4(f01.x, f01.y, f23.x, f23.y);
}
__device__ __forceinline__ float tanh_fast(float x) {
    float t;
    asm("tanh.approx.f32 %0, %1;" : "=f"(t) : "f"(x));
    return t;
}
__device__ __forceinline__ float sig_fast(float x) {
    return 1.f / (1.f + __expf(-x));
}
__device__ __forceinline__ float4 sig4f(float4 a) {
    return make_float4(sig_fast(a.x), sig_fast(a.y), sig_fast(a.z), sig_fast(a.w));
}
__device__ __forceinline__ float4 f4add(float4 a, float4 b) {
    return make_float4(a.x + b.x, a.y + b.y, a.z + b.z, a.w + b.w);
}
__device__ __forceinline__ float4 f4add3(float4 a, float4 b, float4 c) {
    return make_float4(a.x + b.x + c.x, a.y + b.y + c.y, a.z + b.z + c.z, a.w + b.w + c.w);
}

// ---------------- cvt16: fp32 -> fp16 plane [M x 128] zero-padded ----------------
__global__ void k_cvt16(const float* __restrict__ src, int Ksrc, int srcStride,
                        __half* __restrict__ dst, int M) {
    int idx = blockIdx.x * blockDim.x + threadIdx.x;
    if (idx >= M * 32) return;
    int r = idx >> 5, g = idx & 31;
    int c = g * 4;
    float4 v = make_float4(0.f, 0.f, 0.f, 0.f);
    if (c + 3 < Ksrc) v = *reinterpret_cast<const float4*>(src + (size_t)r * srcStride + c);
    __half2 h01 = __floats2half2_rn(v.x, v.y);
    __half2 h23 = __floats2half2_rn(v.z, v.w);
    uint2 o;
    o.x = *reinterpret_cast<uint32_t*>(&h01);
    o.y = *reinterpret_cast<uint32_t*>(&h23);
    *reinterpret_cast<uint2*>(dst + (size_t)r * 128 + c) = o;
}

// ---------------- norm16: agg/(denom+eps) -> fp16 plane ----------------
__global__ void k_norm16(const float* __restrict__ src, const float* __restrict__ denom,
                         __half* __restrict__ dst, int M) {
    int idx = blockIdx.x * blockDim.x + threadIdx.x;
    if (idx >= M * 32) return;
    int r = idx >> 5, g = idx & 31;
    int c = g * 4;
    float inv = 1.f / (denom[r] + 1e-6f);
    float4 v = *reinterpret_cast<const float4*>(src + (size_t)r * 128 + c);
    __half2 h01 = __floats2half2_rn(v.x * inv, v.y * inv);
    __half2 h23 = __floats2half2_rn(v.z * inv, v.w * inv);
    uint2 o;
    o.x = *reinterpret_cast<uint32_t*>(&h01);
    o.y = *reinterpret_cast<uint32_t*>(&h23);
    *reinterpret_cast<uint2*>(dst + (size_t)r * 128 + c) = o;
}

// ---------------- fp16 single-MMA GEMM, A-resident multi-N ----------------
#define S16_A 0
#define S16_B 32768
#define HM16_SMEM 65536

template <int NT>
__global__ __launch_bounds__(256) void k_hmma16_nt(
    const __half* __restrict__ A16, const __half* __restrict__ B16,
    __half* __restrict__ C, int M) {
    extern __shared__ char smem[];
    const uint32_t sb = smem_u32(smem);
    const int tid  = threadIdx.x;
    const int lane = tid & 31;
    const int wid  = tid >> 5;
    const int warpM = wid & 3;
    const int warpN = wid >> 2;
    const int rowBase = blockIdx.x * 128;
    const int N = NT * 128;

    {
        int r = tid >> 4, g = tid & 15;
        #pragma unroll
        for (int i = 0; i < 8; i++) {
            int rr = r + i * 16;
            int ga = rowBase + rr;  if (ga > M - 1) ga = M - 1;
            *reinterpret_cast<uint4*>(smem + S16_A + swz(rr, g)) =
                *reinterpret_cast<const uint4*>(A16 + (size_t)ga * 128 + g * 8);
        }
    }

    #pragma unroll
    for (int nt = 0; nt < NT; nt++) {
        {
            int r = tid >> 4, g = tid & 15;
            #pragma unroll
            for (int i = 0; i < 8; i++) {
                int rr = r + i * 16;
                *reinterpret_cast<uint4*>(smem + S16_B + swz(rr, g)) =
                    *reinterpret_cast<const uint4*>(B16 + (size_t)(nt * 128 + rr) * 128 + g * 8);
            }
        }
        __syncthreads();

        float acc[2][8][4];
        #pragma unroll
        for (int i = 0; i < 2; i++)
            #pragma unroll
            for (int j = 0; j < 8; j++)
                #pragma unroll
                for (int q = 0; q < 4; q++) acc[i][j][q] = 0.f;

        #pragma unroll
        for (int ks = 0; ks < 8; ks++) {
            uint32_t a[2][4];
            #pragma unroll
            for (int mi = 0; mi < 2; mi++) {
                int row  = warpM * 32 + mi * 16 + (lane & 15);
                int unit = 2 * ks + (lane >> 4);
                ldm_x4(a[mi], sb + S16_A + swz(row, unit));
            }
            #pragma unroll
            for (int nbp = 0; nbp < 4; nbp++) {
                int nrow = warpN * 64 + nbp * 16 + (lane & 7) + ((lane >> 4) << 3);
                int unit = 2 * ks + ((lane >> 3) & 1);
                uint32_t b[4];
                ldm_x4(b, sb + S16_B + swz(nrow, unit));
                #pragma unroll
                for (int mi = 0; mi < 2; mi++) {
                    #pragma unroll
                    for (int na = 0; na < 2; na++)
                        mma_f16(acc[mi][nbp * 2 + na], a[mi], b[na * 2], b[na * 2 + 1]);
                }
            }
        }

        #pragma unroll
        for (int mi = 0; mi < 2; mi++) {
            int r0 = rowBase + warpM * 32 + mi * 16 + (lane >> 2);
            #pragma unroll
            for (int nb = 0; nb < 8; nb++) {
                int col = nt * 128 + warpN * 64 + nb * 8 + (lane & 3) * 2;
                if (r0 < M)
                    *reinterpret_cast<__half2*>(C + (size_t)r0 * N + col) =
                        __floats2half2_rn(acc[mi][nb][0], acc[mi][nb][1]);
                if (r0 + 8 < M)
                    *reinterpret_cast<__half2*>(C + (size_t)(r0 + 8) * N + col) =
                        __floats2half2_rn(acc[mi][nb][2], acc[mi][nb][3]);
            }
        }
        __syncthreads();
    }
}

// ---------------- out GEMM on fp16 HMMA + relu + LayerNorm ----------------
__global__ __launch_bounds__(256) void k_out16(
    const __half* __restrict__ A16,   // agg16 [M x 128]
    const __half* __restrict__ B16,   // Wh16 [128 x 128]
    const float* __restrict__ lng, const float* __restrict__ lnb,
    float* __restrict__ C, int M) {
    extern __shared__ char smem[];
    const uint32_t sb = smem_u32(smem);
    const int tid  = threadIdx.x;
    const int lane = tid & 31;
    const int wid  = tid >> 5;
    const int warpM = wid & 3;
    const int warpN = wid >> 2;
    const int rowBase = blockIdx.x * 128;

    {
        int r = tid >> 4, g = tid & 15;
        #pragma unroll
        for (int i = 0; i < 8; i++) {
            int rr = r + i * 16;
            int ga = rowBase + rr;  if (ga > M - 1) ga = M - 1;
            *reinterpret_cast<uint4*>(smem + S16_A + swz(rr, g)) =
                *reinterpret_cast<const uint4*>(A16 + (size_t)ga * 128 + g * 8);
            *reinterpret_cast<uint4*>(smem + S16_B + swz(rr, g)) =
                *reinterpret_cast<const uint4*>(B16 + (size_t)rr * 128 + g * 8);
        }
    }
    __syncthreads();

    float acc[2][8][4];
    #pragma unroll
    for (int i = 0; i < 2; i++)
        #pragma unroll
        for (int j = 0; j < 8; j++)
            #pragma unroll
            for (int q = 0; q < 4; q++) acc[i][j][q] = 0.f;

    #pragma unroll
    for (int ks = 0; ks < 8; ks++) {
        uint32_t a[2][4];
        #pragma unroll
        for (int mi = 0; mi < 2; mi++) {
            int row  = warpM * 32 + mi * 16 + (lane & 15);
            int unit = 2 * ks + (lane >> 4);
            ldm_x4(a[mi], sb + S16_A + swz(row, unit));
        }
        #pragma unroll
        for (int nbp = 0; nbp < 4; nbp++) {
            int nrow = warpN * 64 + nbp * 16 + (lane & 7) + ((lane >> 4) << 3);
            int unit = 2 * ks + ((lane >> 3) & 1);
            uint32_t b[4];
            ldm_x4(b, sb + S16_B + swz(nrow, unit));
            #pragma unroll
            for (int mi = 0; mi < 2; mi++) {
                #pragma unroll
                for (int na = 0; na < 2; na++)
                    mma_f16(acc[mi][nbp * 2 + na], a[mi], b[na * 2], b[na * 2 + 1]);
            }
        }
    }
    __syncthreads();   // all smem tile reads done; reuse for LN stats

    float* s_sum = reinterpret_cast<float*>(smem);          // [128][2]
    float* s_sq  = reinterpret_cast<float*>(smem + 1024);   // [128][2]

    #pragma unroll
    for (int mi = 0; mi < 2; mi++) {
        #pragma unroll
        for (int half = 0; half < 2; half++) {
            float sum = 0.f, sq = 0.f;
            #pragma unroll
            for (int nb = 0; nb < 8; nb++) {
                float v0 = fmaxf(acc[mi][nb][half * 2], 0.f);
                float v1 = fmaxf(acc[mi][nb][half * 2 + 1], 0.f);
                acc[mi][nb][half * 2]     = v0;
                acc[mi][nb][half * 2 + 1] = v1;
                sum += v0 + v1;
                sq  += v0 * v0 + v1 * v1;
            }
            sum += __shfl_xor_sync(0xffffffffu, sum, 1);
            sq  += __shfl_xor_sync(0xffffffffu, sq, 1);
            sum += __shfl_xor_sync(0xffffffffu, sum, 2);
            sq  += __shfl_xor_sync(0xffffffffu, sq, 2);
            if ((lane & 3) == 0) {
                int r = warpM * 32 + mi * 16 + half * 8 + (lane >> 2);
                s_sum[r * 2 + warpN] = sum;
                s_sq [r * 2 + warpN] = sq;
            }
        }
    }
    __syncthreads();

    #pragma unroll
    for (int mi = 0; mi < 2; mi++) {
        #pragma unroll
        for (int half = 0; half < 2; half++) {
            int r = warpM * 32 + mi * 16 + half * 8 + (lane >> 2);
            float sum = s_sum[r * 2] + s_sum[r * 2 + 1];
            float sq  = s_sq [r * 2] + s_sq [r * 2 + 1];
            float mean = sum * (1.f / 128.f);
            float var  = sq * (1.f / 128.f) - mean * mean;
            float inv  = rsqrtf(var + 1e-5f);
            int gr = rowBase + r;
            if (gr < M) {
                #pragma unroll
                for (int nb = 0; nb < 8; nb++) {
                    int col = warpN * 64 + nb * 8 + (lane & 3) * 2;
                    float o0 = lng[col]     * (acc[mi][nb][half * 2]     - mean) * inv + lnb[col];
                    float o1 = lng[col + 1] * (acc[mi][nb][half * 2 + 1] - mean) * inv + lnb[col + 1];
                    *reinterpret_cast<float2*>(C + (size_t)gr * 128 + col) = make_float2(o0, o1);
                }
            }
        }
    }
}

// ---------------- init (zero scratch) ----------------
__global__ void k_init() {
    int i = blockIdx.x * blockDim.x + threadIdx.x;
    if (i < NNEW * H_DIM) g_agg[i] = 0.f;
    if (i < NNEW) g_denom[i] = 0.f;
}

// ---------------- relation-table projections (tiny, fp32; bqr folded into wqr) ----------------
__global__ void k_rel(const float* __restrict__ rel_table,
                      const float* __restrict__ Wr,
                      const float* __restrict__ Wqr,
                      const float* __restrict__ W_ih,
                      const float* __restrict__ bqr) {
    __shared__ float sh[D_EMB];
    int r = blockIdx.x;
    int j = threadIdx.x;  // 384 threads
    if (j < D_EMB) sh[j] = rel_table[r * D_EMB + j];
    __syncthreads();
    float s = 0.f;
    const float* wrow = W_ih + j * (2 * D_EMB) + D_EMB;
    #pragma unroll 4
    for (int d = 0; d < D_EMB; d++) s = fmaf(sh[d], wrow[d], s);
    g_rel_gru[r * G3H + j] = s;
    if (j < H_DIM) {
        float s1 = 0.f, s2 = 0.f;
        #pragma unroll 4
        for (int d = 0; d < D_EMB; d++) {
            s1 = fmaf(sh[d], Wr[j * D_EMB + d], s1);
            s2 = fmaf(sh[d], Wqr[j * D_EMB + d], s2);
        }
        g_rel_wr[r * H_DIM + j] = s1;
        g_rel_wqr[r * H_DIM + j] = s2 + bqr[j];
    }
}

// ---------------- fused edge pass: logit -> ex -> GRU gates -> scatter ex*msg + ex ----------------
__global__ __launch_bounds__(256) void k_edge(
    const int* __restrict__ head, const int* __restrict__ rel,
    const int* __restrict__ ent, const int* __restrict__ tail,
    const int* __restrict__ qidx,
    const float* __restrict__ Wa, const float* __restrict__ ba,
    const float* __restrict__ bih, const float* __restrict__ bhh) {
    int e = blockIdx.x * 8 + (threadIdx.x >> 5);
    if (e >= E_EDGES) return;
    int lane = threadIdx.x & 31;
    int hd = head[e], rl = rel[e], en = ent[e], tl = tail[e], qq = qidx[e];

    // ---- logit ----
    const float4* rw = reinterpret_cast<const float4*>(g_rel_wr) + (size_t)rl * 32;
    const float4* qw = reinterpret_cast<const float4*>(g_rel_wqr) + (size_t)qq * 32;
    float4 a  = ld_half4(g_ns16 + (size_t)hd * 128 + lane * 4);
    float4 b  = rw[lane];
    float4 c  = qw[lane];
    float4 wa = reinterpret_cast<const float4*>(Wa)[lane];
    float x0 = fmaxf(a.x + b.x + c.x, 0.f);
    float x1 = fmaxf(a.y + b.y + c.y, 0.f);
    float x2 = fmaxf(a.z + b.z + c.z, 0.f);
    float x3 = fmaxf(a.w + b.w + c.w, 0.f);
    float s = x0 * wa.x + x1 * wa.y + x2 * wa.z + x3 * wa.w;
    #pragma unroll
    for (int m = 16; m; m >>= 1) s += __shfl_xor_sync(0xffffffffu, s, m);
    float ex = __expf(s + ba[0]);   // all lanes hold ex; logits O(1), no max-shift needed

    // ---- GRU gates ----
    const __half* ep = g_ent_proj + (size_t)en * G3H;
    const __half* nh = g_node_hh + (size_t)hd * G3H;
    const float4* rg = reinterpret_cast<const float4*>(g_rel_gru) + (size_t)rl * 96;
    const float4* bi = reinterpret_cast<const float4*>(bih);
    const float4* bh = reinterpret_cast<const float4*>(bhh);

    float4 ep_r = ld_half4(ep + lane * 4);
    float4 ep_z = ld_half4(ep + 128 + lane * 4);
    float4 ep_n = ld_half4(ep + 256 + lane * 4);
    float4 nh_r = ld_half4(nh + lane * 4);
    float4 nh_z = ld_half4(nh + 128 + lane * 4);
    float4 nh_n = ld_half4(nh + 256 + lane * 4);

    float4 gr = f4add3(ep_r, rg[lane],      bi[lane]);
    float4 hr = f4add (nh_r, bh[lane]);
    float4 gz = f4add3(ep_z, rg[lane + 32], bi[lane + 32]);
    float4 hz = f4add (nh_z, bh[lane + 32]);
    float4 gn = f4add3(ep_n, rg[lane + 64], bi[lane + 64]);
    float4 hn = f4add (nh_n, bh[lane + 64]);

    float4 r4 = sig4f(f4add(gr, hr));
    float4 z4 = sig4f(f4add(gz, hz));
    float4 n4;
    n4.x = tanh_fast(gn.x + r4.x * hn.x);
    n4.y = tanh_fast(gn.y + r4.y * hn.y);
    n4.z = tanh_fast(gn.z + r4.z * hn.z);
    n4.w = tanh_fast(gn.w + r4.w * hn.w);

    float4 hs = ld_half4(g_A16 + (size_t)hd * 128 + lane * 4);

    // ---- scatter ex*msg and ex (division hoisted to k_norm16) ----
    float mx = ex * ((1.f - z4.x) * n4.x + z4.x * hs.x);
    float my = ex * ((1.f - z4.y) * n4.y + z4.y * hs.y);
    float mz = ex * ((1.f - z4.z) * n4.z + z4.z * hs.z);
    float mw = ex * ((1.f - z4.w) * n4.w + z4.w * hs.w);

    float* dst = &g_agg[(size_t)tl * H_DIM + lane * 4];
    asm volatile("red.global.add.v4.f32 [%0], {%1,%2,%3,%4};"
                 :: "l"(dst), "f"(mx), "f"(my), "f"(mz), "f"(mw) : "memory");
    if (lane == 0) {
        asm volatile("red.global.add.f32 [%0], %1;"
                     :: "l"(&g_denom[tl]), "f"(ex) : "memory");
    }
}

// ---------------- launcher ----------------
extern "C" void kernel_launch(void* const* d_in, const int* in_sizes, int n_in,
                              void* d_out, int out_size) {
    const int*   head      = (const int*)d_in[0];
    const int*   rel       = (const int*)d_in[1];
    const int*   ent       = (const int*)d_in[2];
    const int*   tail      = (const int*)d_in[3];
    const int*   qidx      = (const int*)d_in[4];
    const float* node_emb  = (const float*)d_in[5];
    const float* ent_table = (const float*)d_in[6];
    const float* rel_table = (const float*)d_in[7];
    const float* Ws        = (const float*)d_in[8];
    const float* Wr        = (const float*)d_in[9];
    const float* Wqr       = (const float*)d_in[10];
    const float* bqr       = (const float*)d_in[11];
    const float* Wa        = (const float*)d_in[12];
    const float* ba        = (const float*)d_in[13];
    const float* W_ih      = (const float*)d_in[14];
    const float* W_hh      = (const float*)d_in[15];
    const float* bih       = (const float*)d_in[16];
    const float* bhh       = (const float*)d_in[17];
    const float* Wh        = (const float*)d_in[18];
    const float* lng       = (const float*)d_in[19];
    const float* lnb       = (const float*)d_in[20];
    float* out = (float*)d_out;

    float *p_agg, *p_denom;
    __half *p_ns16, *p_node_hh, *p_ent_proj, *p_A16, *p_E16, *p_Ws16, *p_Whh16, *p_Wih16, *p_Wh16, *p_agg16;
    cudaGetSymbolAddress((void**)&p_ns16,     g_ns16);
    cudaGetSymbolAddress((void**)&p_node_hh,  g_node_hh);
    cudaGetSymbolAddress((void**)&p_ent_proj, g_ent_proj);
    cudaGetSymbolAddress((void**)&p_agg,      g_agg);
    cudaGetSymbolAddress((void**)&p_denom,    g_denom);
    cudaGetSymbolAddress((void**)&p_agg16,    g_agg16);
    cudaGetSymbolAddress((void**)&p_A16,   g_A16);
    cudaGetSymbolAddress((void**)&p_E16,   g_E16);
    cudaGetSymbolAddress((void**)&p_Ws16,  g_Ws16);
    cudaGetSymbolAddress((void**)&p_Whh16, g_Whh16);
    cudaGetSymbolAddress((void**)&p_Wih16, g_Wih16);
    cudaGetSymbolAddress((void**)&p_Wh16,  g_Wh16);

    cudaFuncSetAttribute(k_hmma16_nt<1>, cudaFuncAttributeMaxDynamicSharedMemorySize, HM16_SMEM);
    cudaFuncSetAttribute(k_hmma16_nt<3>, cudaFuncAttributeMaxDynamicSharedMemorySize, HM16_SMEM);
    cudaFuncSetAttribute(k_out16, cudaFuncAttributeMaxDynamicSharedMemorySize, HM16_SMEM);

    k_init<<<(NNEW * H_DIM + 255) / 256, 256>>>();
    k_rel<<<NREL, G3H>>>(rel_table, Wr, Wqr, W_ih, bqr);
    // fp16 plane conversions
    k_cvt16<<<(NOLD * 32 + 255) / 256, 256>>>(node_emb, H_DIM, H_DIM, p_A16, NOLD);
    k_cvt16<<<(128 * 32 + 255) / 256, 256>>>(Ws, H_DIM, H_DIM, p_Ws16, 128);
    k_cvt16<<<(NENT * 32 + 255) / 256, 256>>>(ent_table, D_EMB, D_EMB, p_E16, NENT);
    k_cvt16<<<(G3H * 32 + 255) / 256, 256>>>(W_hh, H_DIM, H_DIM,     p_Whh16, G3H);
    k_cvt16<<<(G3H * 32 + 255) / 256, 256>>>(W_ih, D_EMB, 2 * D_EMB, p_Wih16, G3H);
    k_cvt16<<<(128 * 32 + 255) / 256, 256>>>(Wh, H_DIM, H_DIM, p_Wh16, 128);
    // precompute GEMMs (all fp16 single-MMA)
    {
        int grid = (NOLD + 127) / 128;
        k_hmma16_nt<1><<<grid, 256, HM16_SMEM>>>(p_A16, p_Ws16, p_ns16, NOLD);
        k_hmma16_nt<3><<<grid, 256, HM16_SMEM>>>(p_A16, p_Whh16, p_node_hh, NOLD);
        int gride = (NENT + 127) / 128;
        k_hmma16_nt<3><<<gride, 256, HM16_SMEM>>>(p_E16, p_Wih16, p_ent_proj, NENT);
    }
    // fused edge pass: logit + exp + gates + scatter (ex*msg, ex)
    k_edge<<<E_EDGES / 8, 256>>>(head, rel, ent, tail, qidx, Wa, ba, bih, bhh);
    // normalize agg by denom, convert to fp16 plane
    k_norm16<<<(NNEW * 32 + 255) / 256, 256>>>(p_agg, p_denom, p_agg16, NNEW);
    // out GEMM + relu + LayerNorm
    k_out16<<<(NNEW + 127) / 128, 256, HM16_SMEM>>>(p_agg16, p_Wh16, lng, lnb, out, NNEW);
}

// round 16
// speedup vs baseline: 1.2747x; 1.2747x over previous
#include <cuda_runtime.h>
#include <cuda_fp16.h>
#include <cstdint>
#include <math.h>

#define E_EDGES 500000
#define NOLD    100000
#define NNEW    100000
#define NENT    100000
#define NREL    500
#define D_EMB   100
#define H_DIM   128
#define G3H     384

// ---------------- scratch (device globals; no allocation allowed) ----------------
__device__ __align__(16) __half   g_ns16[NOLD * H_DIM];        // node_emb @ Ws^T (fp16)
__device__ __align__(16) __half   g_node_hh[NOLD * G3H];       // node_emb @ W_hh^T (fp16)
__device__ __align__(16) __half   g_ent_proj[NENT * G3H];      // ent_table @ W_ih[:, :100]^T (fp16)
__device__ __align__(16) float    g_rel_wr[NREL * H_DIM];
__device__ __align__(16) float    g_rel_wqr[NREL * H_DIM];     // includes +bqr folded in
__device__ __align__(16) float    g_rel_gru[NREL * G3H];
__device__ float                  g_ex[E_EDGES];
__device__ float                  g_denom[NNEW];
__device__ __align__(16) float    g_agg[NNEW * H_DIM];
__device__ __align__(16) __half   g_agg16[NNEW * H_DIM];
// fp16 planes (zero-padded to K=128)
__device__ __align__(16) __half g_A16[NOLD * 128];     // node_emb fp16 (GEMM A + hs gather source)
__device__ __align__(16) __half g_E16[NENT * 128];     // ent_table fp16
__device__ __align__(16) __half g_Ws16[128 * 128];
__device__ __align__(16) __half g_Whh16[G3H * 128];
__device__ __align__(16) __half g_Wih16[G3H * 128];
__device__ __align__(16) __half g_Wh16[128 * 128];

// ---------------- helpers ----------------
__device__ __forceinline__ uint32_t smem_u32(const void* p) {
    uint32_t a;
    asm("{ .reg .u64 t; cvta.to.shared.u64 t, %1; cvt.u32.u64 %0, t; }" : "=r"(a) : "l"(p));
    return a;
}
__device__ __forceinline__ void ldm_x4(uint32_t* r, uint32_t addr) {
    asm volatile("ldmatrix.sync.aligned.m8n8.x4.shared.b16 {%0,%1,%2,%3}, [%4];"
                 : "=r"(r[0]), "=r"(r[1]), "=r"(r[2]), "=r"(r[3]) : "r"(addr));
}
__device__ __forceinline__ void mma_f16(float* d, const uint32_t* a, uint32_t b0, uint32_t b1) {
    asm volatile(
        "mma.sync.aligned.m16n8k16.row.col.f32.f16.f16.f32 "
        "{%0,%1,%2,%3}, {%4,%5,%6,%7}, {%8,%9}, {%0,%1,%2,%3};"
        : "+f"(d[0]), "+f"(d[1]), "+f"(d[2]), "+f"(d[3])
        : "r"(a[0]), "r"(a[1]), "r"(a[2]), "r"(a[3]), "r"(b0), "r"(b1));
}
__device__ __forceinline__ uint32_t swz(int r, int u) {
    return (uint32_t)(r * 256) + ((uint32_t)((u & 8) | ((u & 7) ^ (r & 7))) << 4);
}
__device__ __forceinline__ float4 ld_half4(const __half* p) {
    uint2 u = *reinterpret_cast<const uint2*>(p);
    __half2 h01 = *reinterpret_cast<__half2*>(&u.x);
    __half2 h23 = *reinterpret_cast<__half2*>(&u.y);
    float2 f01 = __half22float2(h01);
    float2 f23 = __half22float2(h23);
    return make_float4(f01.x, f01.y, f23.x, f23.y);
}
__device__ __forceinline__ float tanh_fast(float x) {
    float t;
    asm("tanh.approx.f32 %0, %1;" : "=f"(t) : "f"(x));
    return t;
}
__device__ __forceinline__ float sig_fast(float x) {
    return 1.f / (1.f + __expf(-x));
}
__device__ __forceinline__ float4 sig4f(float4 a) {
    return make_float4(sig_fast(a.x), sig_fast(a.y), sig_fast(a.z), sig_fast(a.w));
}
__device__ __forceinline__ float4 f4add(float4 a, float4 b) {
    return make_float4(a.x + b.x, a.y + b.y, a.z + b.z, a.w + b.w);
}
__device__ __forceinline__ float4 f4add3(float4 a, float4 b, float4 c) {
    return make_float4(a.x + b.x + c.x, a.y + b.y + c.y, a.z + b.z + c.z, a.w + b.w + c.w);
}

// ---------------- cvt16: fp32 -> fp16 plane [M x 128] zero-padded ----------------
__global__ void k_cvt16(const float* __restrict__ src, int Ksrc, int srcStride,
                        __half* __restrict__ dst, int M) {
    int idx = blockIdx.x * blockDim.x + threadIdx.x;
    if (idx >= M * 32) return;
    int r = idx >> 5, g = idx & 31;
    int c = g * 4;
    float4 v = make_float4(0.f, 0.f, 0.f, 0.f);
    if (c + 3 < Ksrc) v = *reinterpret_cast<const float4*>(src + (size_t)r * srcStride + c);
    __half2 h01 = __floats2half2_rn(v.x, v.y);
    __half2 h23 = __floats2half2_rn(v.z, v.w);
    uint2 o;
    o.x = *reinterpret_cast<uint32_t*>(&h01);
    o.y = *reinterpret_cast<uint32_t*>(&h23);
    *reinterpret_cast<uint2*>(dst + (size_t)r * 128 + c) = o;
}

// ---------------- fp16 single-MMA GEMM, A-resident multi-N ----------------
#define S16_A 0
#define S16_B 32768
#define HM16_SMEM 65536

template <int NT>
__global__ __launch_bounds__(256) void k_hmma16_nt(
    const __half* __restrict__ A16, const __half* __restrict__ B16,
    __half* __restrict__ C, int M) {
    extern __shared__ char smem[];
    const uint32_t sb = smem_u32(smem);
    const int tid  = threadIdx.x;
    const int lane = tid & 31;
    const int wid  = tid >> 5;
    const int warpM = wid & 3;
    const int warpN = wid >> 2;
    const int rowBase = blockIdx.x * 128;
    const int N = NT * 128;

    {
        int r = tid >> 4, g = tid & 15;
        #pragma unroll
        for (int i = 0; i < 8; i++) {
            int rr = r + i * 16;
            int ga = rowBase + rr;  if (ga > M - 1) ga = M - 1;
            *reinterpret_cast<uint4*>(smem + S16_A + swz(rr, g)) =
                *reinterpret_cast<const uint4*>(A16 + (size_t)ga * 128 + g * 8);
        }
    }

    #pragma unroll
    for (int nt = 0; nt < NT; nt++) {
        {
            int r = tid >> 4, g = tid & 15;
            #pragma unroll
            for (int i = 0; i < 8; i++) {
                int rr = r + i * 16;
                *reinterpret_cast<uint4*>(smem + S16_B + swz(rr, g)) =
                    *reinterpret_cast<const uint4*>(B16 + (size_t)(nt * 128 + rr) * 128 + g * 8);
            }
        }
        __syncthreads();

        float acc[2][8][4];
        #pragma unroll
        for (int i = 0; i < 2; i++)
            #pragma unroll
            for (int j = 0; j < 8; j++)
                #pragma unroll
                for (int q = 0; q < 4; q++) acc[i][j][q] = 0.f;

        #pragma unroll
        for (int ks = 0; ks < 8; ks++) {
            uint32_t a[2][4];
            #pragma unroll
            for (int mi = 0; mi < 2; mi++) {
                int row  = warpM * 32 + mi * 16 + (lane & 15);
                int unit = 2 * ks + (lane >> 4);
                ldm_x4(a[mi], sb + S16_A + swz(row, unit));
            }
            #pragma unroll
            for (int nbp = 0; nbp < 4; nbp++) {
                int nrow = warpN * 64 + nbp * 16 + (lane & 7) + ((lane >> 4) << 3);
                int unit = 2 * ks + ((lane >> 3) & 1);
                uint32_t b[4];
                ldm_x4(b, sb + S16_B + swz(nrow, unit));
                #pragma unroll
                for (int mi = 0; mi < 2; mi++) {
                    #pragma unroll
                    for (int na = 0; na < 2; na++)
                        mma_f16(acc[mi][nbp * 2 + na], a[mi], b[na * 2], b[na * 2 + 1]);
                }
            }
        }

        #pragma unroll
        for (int mi = 0; mi < 2; mi++) {
            int r0 = rowBase + warpM * 32 + mi * 16 + (lane >> 2);
            #pragma unroll
            for (int nb = 0; nb < 8; nb++) {
                int col = nt * 128 + warpN * 64 + nb * 8 + (lane & 3) * 2;
                if (r0 < M)
                    *reinterpret_cast<__half2*>(C + (size_t)r0 * N + col) =
                        __floats2half2_rn(acc[mi][nb][0], acc[mi][nb][1]);
                if (r0 + 8 < M)
                    *reinterpret_cast<__half2*>(C + (size_t)(r0 + 8) * N + col) =
                        __floats2half2_rn(acc[mi][nb][2], acc[mi][nb][3]);
            }
        }
        __syncthreads();
    }
}

// ---------------- out GEMM on fp16 HMMA + relu + LayerNorm ----------------
__global__ __launch_bounds__(256) void k_out16(
    const __half* __restrict__ A16,   // agg16 [M x 128]
    const __half* __restrict__ B16,   // Wh16 [128 x 128]
    const float* __restrict__ lng, const float* __restrict__ lnb,
    float* __restrict__ C, int M) {
    extern __shared__ char smem[];
    const uint32_t sb = smem_u32(smem);
    const int tid  = threadIdx.x;
    const int lane = tid & 31;
    const int wid  = tid >> 5;
    const int warpM = wid & 3;
    const int warpN = wid >> 2;
    const int rowBase = blockIdx.x * 128;

    {
        int r = tid >> 4, g = tid & 15;
        #pragma unroll
        for (int i = 0; i < 8; i++) {
            int rr = r + i * 16;
            int ga = rowBase + rr;  if (ga > M - 1) ga = M - 1;
            *reinterpret_cast<uint4*>(smem + S16_A + swz(rr, g)) =
                *reinterpret_cast<const uint4*>(A16 + (size_t)ga * 128 + g * 8);
            *reinterpret_cast<uint4*>(smem + S16_B + swz(rr, g)) =
                *reinterpret_cast<const uint4*>(B16 + (size_t)rr * 128 + g * 8);
        }
    }
    __syncthreads();

    float acc[2][8][4];
    #pragma unroll
    for (int i = 0; i < 2; i++)
        #pragma unroll
        for (int j = 0; j < 8; j++)
            #pragma unroll
            for (int q = 0; q < 4; q++) acc[i][j][q] = 0.f;

    #pragma unroll
    for (int ks = 0; ks < 8; ks++) {
        uint32_t a[2][4];
        #pragma unroll
        for (int mi = 0; mi < 2; mi++) {
            int row  = warpM * 32 + mi * 16 + (lane & 15);
            int unit = 2 * ks + (lane >> 4);
            ldm_x4(a[mi], sb + S16_A + swz(row, unit));
        }
        #pragma unroll
        for (int nbp = 0; nbp < 4; nbp++) {
            int nrow = warpN * 64 + nbp * 16 + (lane & 7) + ((lane >> 4) << 3);
            int unit = 2 * ks + ((lane >> 3) & 1);
            uint32_t b[4];
            ldm_x4(b, sb + S16_B + swz(nrow, unit));
            #pragma unroll
            for (int mi = 0; mi < 2; mi++) {
                #pragma unroll
                for (int na = 0; na < 2; na++)
                    mma_f16(acc[mi][nbp * 2 + na], a[mi], b[na * 2], b[na * 2 + 1]);
            }
        }
    }
    __syncthreads();   // all smem tile reads done; reuse for LN stats

    float* s_sum = reinterpret_cast<float*>(smem);          // [128][2]
    float* s_sq  = reinterpret_cast<float*>(smem + 1024);   // [128][2]

    #pragma unroll
    for (int mi = 0; mi < 2; mi++) {
        #pragma unroll
        for (int half = 0; half < 2; half++) {
            float sum = 0.f, sq = 0.f;
            #pragma unroll
            for (int nb = 0; nb < 8; nb++) {
                float v0 = fmaxf(acc[mi][nb][half * 2], 0.f);
                float v1 = fmaxf(acc[mi][nb][half * 2 + 1], 0.f);
                acc[mi][nb][half * 2]     = v0;
                acc[mi][nb][half * 2 + 1] = v1;
                sum += v0 + v1;
                sq  += v0 * v0 + v1 * v1;
            }
            sum += __shfl_xor_sync(0xffffffffu, sum, 1);
            sq  += __shfl_xor_sync(0xffffffffu, sq, 1);
            sum += __shfl_xor_sync(0xffffffffu, sum, 2);
            sq  += __shfl_xor_sync(0xffffffffu, sq, 2);
            if ((lane & 3) == 0) {
                int r = warpM * 32 + mi * 16 + half * 8 + (lane >> 2);
                s_sum[r * 2 + warpN] = sum;
                s_sq [r * 2 + warpN] = sq;
            }
        }
    }
    __syncthreads();

    #pragma unroll
    for (int mi = 0; mi < 2; mi++) {
        #pragma unroll
        for (int half = 0; half < 2; half++) {
            int r = warpM * 32 + mi * 16 + half * 8 + (lane >> 2);
            float sum = s_sum[r * 2] + s_sum[r * 2 + 1];
            float sq  = s_sq [r * 2] + s_sq [r * 2 + 1];
            float mean = sum * (1.f / 128.f);
            float var  = sq * (1.f / 128.f) - mean * mean;
            float inv  = rsqrtf(var + 1e-5f);
            int gr = rowBase + r;
            if (gr < M) {
                #pragma unroll
                for (int nb = 0; nb < 8; nb++) {
                    int col = warpN * 64 + nb * 8 + (lane & 3) * 2;
                    float o0 = lng[col]     * (acc[mi][nb][half * 2]     - mean) * inv + lnb[col];
                    float o1 = lng[col + 1] * (acc[mi][nb][half * 2 + 1] - mean) * inv + lnb[col + 1];
                    *reinterpret_cast<float2*>(C + (size_t)gr * 128 + col) = make_float2(o0, o1);
                }
            }
        }
    }
}

// ---------------- init (zero scratch) ----------------
__global__ void k_init() {
    int i = blockIdx.x * blockDim.x + threadIdx.x;
    if (i < NNEW * H_DIM) g_agg[i] = 0.f;
    if (i < NNEW) g_denom[i] = 0.f;
}

// ---------------- relation-table projections (tiny, fp32; bqr folded into wqr) ----------------
__global__ void k_rel(const float* __restrict__ rel_table,
                      const float* __restrict__ Wr,
                      const float* __restrict__ Wqr,
                      const float* __restrict__ W_ih,
                      const float* __restrict__ bqr) {
    __shared__ float sh[D_EMB];
    int r = blockIdx.x;
    int j = threadIdx.x;  // 384 threads
    if (j < D_EMB) sh[j] = rel_table[r * D_EMB + j];
    __syncthreads();
    float s = 0.f;
    const float* wrow = W_ih + j * (2 * D_EMB) + D_EMB;
    #pragma unroll 4
    for (int d = 0; d < D_EMB; d++) s = fmaf(sh[d], wrow[d], s);
    g_rel_gru[r * G3H + j] = s;
    if (j < H_DIM) {
        float s1 = 0.f, s2 = 0.f;
        #pragma unroll 4
        for (int d = 0; d < D_EMB; d++) {
            s1 = fmaf(sh[d], Wr[j * D_EMB + d], s1);
            s2 = fmaf(sh[d], Wqr[j * D_EMB + d], s2);
        }
        g_rel_wr[r * H_DIM + j] = s1;
        g_rel_wqr[r * H_DIM + j] = s2 + bqr[j];
    }
}

// ---------------- pass A: exp(logit) + denom ----------------
__global__ __launch_bounds__(256) void k_logit(
    const int* __restrict__ head, const int* __restrict__ rel,
    const int* __restrict__ qidx, const int* __restrict__ tail,
    const float* __restrict__ Wa, const float* __restrict__ ba) {
    int e = blockIdx.x * 8 + (threadIdx.x >> 5);
    if (e >= E_EDGES) return;
    int lane = threadIdx.x & 31;
    int h = head[e], rl = rel[e], qq = qidx[e];
    const float4* rw = reinterpret_cast<const float4*>(g_rel_wr) + (size_t)rl * 32;
    const float4* qw = reinterpret_cast<const float4*>(g_rel_wqr) + (size_t)qq * 32;
    float4 a = ld_half4(g_ns16 + (size_t)h * 128 + lane * 4);
    float4 b = rw[lane];
    float4 c = qw[lane];
    float4 wa = reinterpret_cast<const float4*>(Wa)[lane];
    float x0 = fmaxf(a.x + b.x + c.x, 0.f);
    float x1 = fmaxf(a.y + b.y + c.y, 0.f);
    float x2 = fmaxf(a.z + b.z + c.z, 0.f);
    float x3 = fmaxf(a.w + b.w + c.w, 0.f);
    float s = x0 * wa.x + x1 * wa.y + x2 * wa.z + x3 * wa.w;
    #pragma unroll
    for (int m = 16; m; m >>= 1) s += __shfl_xor_sync(0xffffffffu, s, m);
    if (lane == 0) {
        float ex = __expf(s + ba[0]);   // logits are O(1): exp safe without max-shift
        g_ex[e] = ex;
        atomicAdd(&g_denom[tail[e]], ex);
    }
}

// ---------------- pass C: GRU gates + weighted scatter-add ----------------
__global__ __launch_bounds__(256) void k_msg(
    const int* __restrict__ head, const int* __restrict__ rel,
    const int* __restrict__ ent, const int* __restrict__ tail,
    const float* __restrict__ bih, const float* __restrict__ bhh) {
    int e = blockIdx.x * 8 + (threadIdx.x >> 5);
    if (e >= E_EDGES) return;
    int lane = threadIdx.x & 31;
    int hd = head[e], rl = rel[e], en = ent[e], tl = tail[e];
    const __half* ep = g_ent_proj + (size_t)en * G3H;
    const __half* nh = g_node_hh + (size_t)hd * G3H;
    const float4* rg = reinterpret_cast<const float4*>(g_rel_gru) + (size_t)rl * 96;
    const float4* bi = reinterpret_cast<const float4*>(bih);
    const float4* bh = reinterpret_cast<const float4*>(bhh);

    float4 ep_r = ld_half4(ep + lane * 4);
    float4 ep_z = ld_half4(ep + 128 + lane * 4);
    float4 ep_n = ld_half4(ep + 256 + lane * 4);
    float4 nh_r = ld_half4(nh + lane * 4);
    float4 nh_z = ld_half4(nh + 128 + lane * 4);
    float4 nh_n = ld_half4(nh + 256 + lane * 4);

    float4 gr = f4add3(ep_r, rg[lane],      bi[lane]);
    float4 hr = f4add (nh_r, bh[lane]);
    float4 gz = f4add3(ep_z, rg[lane + 32], bi[lane + 32]);
    float4 hz = f4add (nh_z, bh[lane + 32]);
    float4 gn = f4add3(ep_n, rg[lane + 64], bi[lane + 64]);
    float4 hn = f4add (nh_n, bh[lane + 64]);

    float4 r4 = sig4f(f4add(gr, hr));
    float4 z4 = sig4f(f4add(gz, hz));
    float4 n4;
    n4.x = tanh_fast(gn.x + r4.x * hn.x);
    n4.y = tanh_fast(gn.y + r4.y * hn.y);
    n4.z = tanh_fast(gn.z + r4.z * hn.z);
    n4.w = tanh_fast(gn.w + r4.w * hn.w);

    float4 hs = ld_half4(g_A16 + (size_t)hd * 128 + lane * 4);
    float alpha = __fdividef(g_ex[e], g_denom[tl] + 1e-6f);

    float mx = alpha * ((1.f - z4.x) * n4.x + z4.x * hs.x);
    float my = alpha * ((1.f - z4.y) * n4.y + z4.y * hs.y);
    float mz = alpha * ((1.f - z4.z) * n4.z + z4.z * hs.z);
    float mw = alpha * ((1.f - z4.w) * n4.w + z4.w * hs.w);

    float* dst = &g_agg[(size_t)tl * H_DIM + lane * 4];
    asm volatile("red.global.add.v4.f32 [%0], {%1,%2,%3,%4};"
                 :: "l"(dst), "f"(mx), "f"(my), "f"(mz), "f"(mw) : "memory");
}

// ---------------- launcher ----------------
extern "C" void kernel_launch(void* const* d_in, const int* in_sizes, int n_in,
                              void* d_out, int out_size) {
    const int*   head      = (const int*)d_in[0];
    const int*   rel       = (const int*)d_in[1];
    const int*   ent       = (const int*)d_in[2];
    const int*   tail      = (const int*)d_in[3];
    const int*   qidx      = (const int*)d_in[4];
    const float* node_emb  = (const float*)d_in[5];
    const float* ent_table = (const float*)d_in[6];
    const float* rel_table = (const float*)d_in[7];
    const float* Ws        = (const float*)d_in[8];
    const float* Wr        = (const float*)d_in[9];
    const float* Wqr       = (const float*)d_in[10];
    const float* bqr       = (const float*)d_in[11];
    const float* Wa        = (const float*)d_in[12];
    const float* ba        = (const float*)d_in[13];
    const float* W_ih      = (const float*)d_in[14];
    const float* W_hh      = (const float*)d_in[15];
    const float* bih       = (const float*)d_in[16];
    const float* bhh       = (const float*)d_in[17];
    const float* Wh        = (const float*)d_in[18];
    const float* lng       = (const float*)d_in[19];
    const float* lnb       = (const float*)d_in[20];
    float* out = (float*)d_out;

    float *p_agg, *p_denom;
    __half *p_ns16, *p_node_hh, *p_ent_proj, *p_A16, *p_E16, *p_Ws16, *p_Whh16, *p_Wih16, *p_Wh16, *p_agg16;
    cudaGetSymbolAddress((void**)&p_ns16,     g_ns16);
    cudaGetSymbolAddress((void**)&p_node_hh,  g_node_hh);
    cudaGetSymbolAddress((void**)&p_ent_proj, g_ent_proj);
    cudaGetSymbolAddress((void**)&p_agg,      g_agg);
    cudaGetSymbolAddress((void**)&p_denom,    g_denom);
    cudaGetSymbolAddress((void**)&p_agg16,    g_agg16);
    cudaGetSymbolAddress((void**)&p_A16,   g_A16);
    cudaGetSymbolAddress((void**)&p_E16,   g_E16);
    cudaGetSymbolAddress((void**)&p_Ws16,  g_Ws16);
    cudaGetSymbolAddress((void**)&p_Whh16, g_Whh16);
    cudaGetSymbolAddress((void**)&p_Wih16, g_Wih16);
    cudaGetSymbolAddress((void**)&p_Wh16,  g_Wh16);

    cudaFuncSetAttribute(k_hmma16_nt<1>, cudaFuncAttributeMaxDynamicSharedMemorySize, HM16_SMEM);
    cudaFuncSetAttribute(k_hmma16_nt<3>, cudaFuncAttributeMaxDynamicSharedMemorySize, HM16_SMEM);
    cudaFuncSetAttribute(k_out16, cudaFuncAttributeMaxDynamicSharedMemorySize, HM16_SMEM);

    k_init<<<(NNEW * H_DIM + 255) / 256, 256>>>();
    k_rel<<<NREL, G3H>>>(rel_table, Wr, Wqr, W_ih, bqr);
    // fp16 plane conversions
    k_cvt16<<<(NOLD * 32 + 255) / 256, 256>>>(node_emb, H_DIM, H_DIM, p_A16, NOLD);
    k_cvt16<<<(128 * 32 + 255) / 256, 256>>>(Ws, H_DIM, H_DIM, p_Ws16, 128);
    k_cvt16<<<(NENT * 32 + 255) / 256, 256>>>(ent_table, D_EMB, D_EMB, p_E16, NENT);
    k_cvt16<<<(G3H * 32 + 255) / 256, 256>>>(W_hh, H_DIM, H_DIM,     p_Whh16, G3H);
    k_cvt16<<<(G3H * 32 + 255) / 256, 256>>>(W_ih, D_EMB, 2 * D_EMB, p_Wih16, G3H);
    k_cvt16<<<(128 * 32 + 255) / 256, 256>>>(Wh, H_DIM, H_DIM, p_Wh16, 128);
    // precompute GEMMs (all fp16 single-MMA)
    {
        int grid = (NOLD + 127) / 128;
        k_hmma16_nt<1><<<grid, 256, HM16_SMEM>>>(p_A16, p_Ws16, p_ns16, NOLD);
        k_hmma16_nt<3><<<grid, 256, HM16_SMEM>>>(p_A16, p_Whh16, p_node_hh, NOLD);
        int gride = (NENT + 127) / 128;
        k_hmma16_nt<3><<<gride, 256, HM16_SMEM>>>(p_E16, p_Wih16, p_ent_proj, NENT);
    }
    // pass A: exp(logit) + denom (single edge pass)
    k_logit<<<E_EDGES / 8, 256>>>(head, rel, qidx, tail, Wa, ba);
    // pass C: gates + weighted scatter
    k_msg<<<E_EDGES / 8, 256>>>(head, rel, ent, tail, bih, bhh);
    // out: agg -> fp16 plane, HMMA GEMM + relu + LayerNorm
    k_cvt16<<<(NNEW * 32 + 255) / 256, 256>>>(p_agg, H_DIM, H_DIM, p_agg16, NNEW);
    k_out16<<<(NNEW + 127) / 128, 256, HM16_SMEM>>>(p_agg16, p_Wh16, lng, lnb, out, NNEW);
}

// round 17
// speedup vs baseline: 1.3296x; 1.0431x over previous
#include <cuda_runtime.h>
#include <cuda_fp16.h>
#include <cstdint>
#include <math.h>

#define E_EDGES 500000
#define NOLD    100000
#define NNEW    100000
#define NENT    100000
#define NREL    500
#define D_EMB   100
#define H_DIM   128
#define G3H     384

// ---------------- scratch (device globals; no allocation allowed) ----------------
__device__ __align__(16) __half   g_ns16[NOLD * H_DIM];        // node_emb @ Ws^T (fp16)
__device__ __align__(16) __half   g_node_hh[NOLD * G3H];       // node_emb @ W_hh^T (fp16)
__device__ __align__(16) __half   g_ent_proj[NENT * G3H];      // ent_table @ W_ih[:, :100]^T (fp16)
__device__ __align__(16) float    g_rel_wr[NREL * H_DIM];
__device__ __align__(16) float    g_rel_wqr[NREL * H_DIM];     // includes +bqr folded in
__device__ __align__(16) float    g_rel_gru[NREL * G3H];
__device__ float                  g_ex[E_EDGES];
__device__ float                  g_denom[NNEW];
__device__ __align__(16) float    g_agg[NNEW * H_DIM];
__device__ __align__(16) __half   g_agg16[NNEW * H_DIM];
// fp16 planes (zero-padded to K=128)
__device__ __align__(16) __half g_A16[NOLD * 128];     // node_emb fp16 (GEMM A + hs gather source)
__device__ __align__(16) __half g_E16[NENT * 128];     // ent_table fp16
__device__ __align__(16) __half g_Ws16[128 * 128];
__device__ __align__(16) __half g_Whh16[G3H * 128];
__device__ __align__(16) __half g_Wih16[G3H * 128];
__device__ __align__(16) __half g_Wh16[128 * 128];

// ---------------- second stream + events (created at static-init time, reused) ----------------
static cudaStream_t g_s2 = nullptr;
static cudaEvent_t  g_evFork = nullptr, g_evA = nullptr, g_evJ = nullptr;
static struct SInit {
    SInit() {
        cudaStreamCreateWithFlags(&g_s2, cudaStreamNonBlocking);
        cudaEventCreateWithFlags(&g_evFork, cudaEventDisableTiming);
        cudaEventCreateWithFlags(&g_evA,    cudaEventDisableTiming);
        cudaEventCreateWithFlags(&g_evJ,    cudaEventDisableTiming);
    }
} g_sinit;

// ---------------- helpers ----------------
__device__ __forceinline__ uint32_t smem_u32(const void* p) {
    uint32_t a;
    asm("{ .reg .u64 t; cvta.to.shared.u64 t, %1; cvt.u32.u64 %0, t; }" : "=r"(a) : "l"(p));
    return a;
}
__device__ __forceinline__ void ldm_x4(uint32_t* r, uint32_t addr) {
    asm volatile("ldmatrix.sync.aligned.m8n8.x4.shared.b16 {%0,%1,%2,%3}, [%4];"
                 : "=r"(r[0]), "=r"(r[1]), "=r"(r[2]), "=r"(r[3]) : "r"(addr));
}
__device__ __forceinline__ void mma_f16(float* d, const uint32_t* a, uint32_t b0, uint32_t b1) {
    asm volatile(
        "mma.sync.aligned.m16n8k16.row.col.f32.f16.f16.f32 "
        "{%0,%1,%2,%3}, {%4,%5,%6,%7}, {%8,%9}, {%0,%1,%2,%3};"
        : "+f"(d[0]), "+f"(d[1]), "+f"(d[2]), "+f"(d[3])
        : "r"(a[0]), "r"(a[1]), "r"(a[2]), "r"(a[3]), "r"(b0), "r"(b1));
}
__device__ __forceinline__ uint32_t swz(int r, int u) {
    return (uint32_t)(r * 256) + ((uint32_t)((u & 8) | ((u & 7) ^ (r & 7))) << 4);
}
__device__ __forceinline__ float4 ld_half4(const __half* p) {
    uint2 u = *reinterpret_cast<const uint2*>(p);
    __half2 h01 = *reinterpret_cast<__half2*>(&u.x);
    __half2 h23 = *reinterpret_cast<__half2*>(&u.y);
    float2 f01 = __half22float2(h01);
    float2 f23 = __half22float2(h23);
    return make_float4(f01.x, f01.y, f23.x, f23.y);
}
__device__ __forceinline__ float tanh_fast(float x) {
    float t;
    asm("tanh.approx.f32 %0, %1;" : "=f"(t) : "f"(x));
    return t;
}
__device__ __forceinline__ float sig_fast(float x) {
    return 1.f / (1.f + __expf(-x));
}
__device__ __forceinline__ float4 sig4f(float4 a) {
    return make_float4(sig_fast(a.x), sig_fast(a.y), sig_fast(a.z), sig_fast(a.w));
}
__device__ __forceinline__ float4 f4add(float4 a, float4 b) {
    return make_float4(a.x + b.x, a.y + b.y, a.z + b.z, a.w + b.w);
}
__device__ __forceinline__ float4 f4add3(float4 a, float4 b, float4 c) {
    return make_float4(a.x + b.x + c.x, a.y + b.y + c.y, a.z + b.z + c.z, a.w + b.w + c.w);
}

// ---------------- cvt16: fp32 -> fp16 plane [M x 128] zero-padded ----------------
__global__ void k_cvt16(const float* __restrict__ src, int Ksrc, int srcStride,
                        __half* __restrict__ dst, int M) {
    int idx = blockIdx.x * blockDim.x + threadIdx.x;
    if (idx >= M * 32) return;
    int r = idx >> 5, g = idx & 31;
    int c = g * 4;
    float4 v = make_float4(0.f, 0.f, 0.f, 0.f);
    if (c + 3 < Ksrc) v = *reinterpret_cast<const float4*>(src + (size_t)r * srcStride + c);
    __half2 h01 = __floats2half2_rn(v.x, v.y);
    __half2 h23 = __floats2half2_rn(v.z, v.w);
    uint2 o;
    o.x = *reinterpret_cast<uint32_t*>(&h01);
    o.y = *reinterpret_cast<uint32_t*>(&h23);
    *reinterpret_cast<uint2*>(dst + (size_t)r * 128 + c) = o;
}

// ---------------- fp16 single-MMA GEMM, A-resident multi-N ----------------
#define S16_A 0
#define S16_B 32768
#define HM16_SMEM 65536

template <int NT>
__global__ __launch_bounds__(256) void k_hmma16_nt(
    const __half* __restrict__ A16, const __half* __restrict__ B16,
    __half* __restrict__ C, int M) {
    extern __shared__ char smem[];
    const uint32_t sb = smem_u32(smem);
    const int tid  = threadIdx.x;
    const int lane = tid & 31;
    const int wid  = tid >> 5;
    const int warpM = wid & 3;
    const int warpN = wid >> 2;
    const int rowBase = blockIdx.x * 128;
    const int N = NT * 128;

    {
        int r = tid >> 4, g = tid & 15;
        #pragma unroll
        for (int i = 0; i < 8; i++) {
            int rr = r + i * 16;
            int ga = rowBase + rr;  if (ga > M - 1) ga = M - 1;
            *reinterpret_cast<uint4*>(smem + S16_A + swz(rr, g)) =
                *reinterpret_cast<const uint4*>(A16 + (size_t)ga * 128 + g * 8);
        }
    }

    #pragma unroll
    for (int nt = 0; nt < NT; nt++) {
        {
            int r = tid >> 4, g = tid & 15;
            #pragma unroll
            for (int i = 0; i < 8; i++) {
                int rr = r + i * 16;
                *reinterpret_cast<uint4*>(smem + S16_B + swz(rr, g)) =
                    *reinterpret_cast<const uint4*>(B16 + (size_t)(nt * 128 + rr) * 128 + g * 8);
            }
        }
        __syncthreads();

        float acc[2][8][4];
        #pragma unroll
        for (int i = 0; i < 2; i++)
            #pragma unroll
            for (int j = 0; j < 8; j++)
                #pragma unroll
                for (int q = 0; q < 4; q++) acc[i][j][q] = 0.f;

        #pragma unroll
        for (int ks = 0; ks < 8; ks++) {
            uint32_t a[2][4];
            #pragma unroll
            for (int mi = 0; mi < 2; mi++) {
                int row  = warpM * 32 + mi * 16 + (lane & 15);
                int unit = 2 * ks + (lane >> 4);
                ldm_x4(a[mi], sb + S16_A + swz(row, unit));
            }
            #pragma unroll
            for (int nbp = 0; nbp < 4; nbp++) {
                int nrow = warpN * 64 + nbp * 16 + (lane & 7) + ((lane >> 4) << 3);
                int unit = 2 * ks + ((lane >> 3) & 1);
                uint32_t b[4];
                ldm_x4(b, sb + S16_B + swz(nrow, unit));
                #pragma unroll
                for (int mi = 0; mi < 2; mi++) {
                    #pragma unroll
                    for (int na = 0; na < 2; na++)
                        mma_f16(acc[mi][nbp * 2 + na], a[mi], b[na * 2], b[na * 2 + 1]);
                }
            }
        }

        #pragma unroll
        for (int mi = 0; mi < 2; mi++) {
            int r0 = rowBase + warpM * 32 + mi * 16 + (lane >> 2);
            #pragma unroll
            for (int nb = 0; nb < 8; nb++) {
                int col = nt * 128 + warpN * 64 + nb * 8 + (lane & 3) * 2;
                if (r0 < M)
                    *reinterpret_cast<__half2*>(C + (size_t)r0 * N + col) =
                        __floats2half2_rn(acc[mi][nb][0], acc[mi][nb][1]);
                if (r0 + 8 < M)
                    *reinterpret_cast<__half2*>(C + (size_t)(r0 + 8) * N + col) =
                        __floats2half2_rn(acc[mi][nb][2], acc[mi][nb][3]);
            }
        }
        __syncthreads();
    }
}

// ---------------- out GEMM on fp16 HMMA + relu + LayerNorm ----------------
__global__ __launch_bounds__(256) void k_out16(
    const __half* __restrict__ A16,   // agg16 [M x 128]
    const __half* __restrict__ B16,   // Wh16 [128 x 128]
    const float* __restrict__ lng, const float* __restrict__ lnb,
    float* __restrict__ C, int M) {
    extern __shared__ char smem[];
    const uint32_t sb = smem_u32(smem);
    const int tid  = threadIdx.x;
    const int lane = tid & 31;
    const int wid  = tid >> 5;
    const int warpM = wid & 3;
    const int warpN = wid >> 2;
    const int rowBase = blockIdx.x * 128;

    {
        int r = tid >> 4, g = tid & 15;
        #pragma unroll
        for (int i = 0; i < 8; i++) {
            int rr = r + i * 16;
            int ga = rowBase + rr;  if (ga > M - 1) ga = M - 1;
            *reinterpret_cast<uint4*>(smem + S16_A + swz(rr, g)) =
                *reinterpret_cast<const uint4*>(A16 + (size_t)ga * 128 + g * 8);
            *reinterpret_cast<uint4*>(smem + S16_B + swz(rr, g)) =
                *reinterpret_cast<const uint4*>(B16 + (size_t)rr * 128 + g * 8);
        }
    }
    __syncthreads();

    float acc[2][8][4];
    #pragma unroll
    for (int i = 0; i < 2; i++)
        #pragma unroll
        for (int j = 0; j < 8; j++)
            #pragma unroll
            for (int q = 0; q < 4; q++) acc[i][j][q] = 0.f;

    #pragma unroll
    for (int ks = 0; ks < 8; ks++) {
        uint32_t a[2][4];
        #pragma unroll
        for (int mi = 0; mi < 2; mi++) {
            int row  = warpM * 32 + mi * 16 + (lane & 15);
            int unit = 2 * ks + (lane >> 4);
            ldm_x4(a[mi], sb + S16_A + swz(row, unit));
        }
        #pragma unroll
        for (int nbp = 0; nbp < 4; nbp++) {
            int nrow = warpN * 64 + nbp * 16 + (lane & 7) + ((lane >> 4) << 3);
            int unit = 2 * ks + ((lane >> 3) & 1);
            uint32_t b[4];
            ldm_x4(b, sb + S16_B + swz(nrow, unit));
            #pragma unroll
            for (int mi = 0; mi < 2; mi++) {
                #pragma unroll
                for (int na = 0; na < 2; na++)
                    mma_f16(acc[mi][nbp * 2 + na], a[mi], b[na * 2], b[na * 2 + 1]);
            }
        }
    }
    __syncthreads();   // all smem tile reads done; reuse for LN stats

    float* s_sum = reinterpret_cast<float*>(smem);          // [128][2]
    float* s_sq  = reinterpret_cast<float*>(smem + 1024);   // [128][2]

    #pragma unroll
    for (int mi = 0; mi < 2; mi++) {
        #pragma unroll
        for (int half = 0; half < 2; half++) {
            float sum = 0.f, sq = 0.f;
            #pragma unroll
            for (int nb = 0; nb < 8; nb++) {
                float v0 = fmaxf(acc[mi][nb][half * 2], 0.f);
                float v1 = fmaxf(acc[mi][nb][half * 2 + 1], 0.f);
                acc[mi][nb][half * 2]     = v0;
                acc[mi][nb][half * 2 + 1] = v1;
                sum += v0 + v1;
                sq  += v0 * v0 + v1 * v1;
            }
            sum += __shfl_xor_sync(0xffffffffu, sum, 1);
            sq  += __shfl_xor_sync(0xffffffffu, sq, 1);
            sum += __shfl_xor_sync(0xffffffffu, sum, 2);
            sq  += __shfl_xor_sync(0xffffffffu, sq, 2);
            if ((lane & 3) == 0) {
                int r = warpM * 32 + mi * 16 + half * 8 + (lane >> 2);
                s_sum[r * 2 + warpN] = sum;
                s_sq [r * 2 + warpN] = sq;
            }
        }
    }
    __syncthreads();

    #pragma unroll
    for (int mi = 0; mi < 2; mi++) {
        #pragma unroll
        for (int half = 0; half < 2; half++) {
            int r = warpM * 32 + mi * 16 + half * 8 + (lane >> 2);
            float sum = s_sum[r * 2] + s_sum[r * 2 + 1];
            float sq  = s_sq [r * 2] + s_sq [r * 2 + 1];
            float mean = sum * (1.f / 128.f);
            float var  = sq * (1.f / 128.f) - mean * mean;
            float inv  = rsqrtf(var + 1e-5f);
            int gr = rowBase + r;
            if (gr < M) {
                #pragma unroll
                for (int nb = 0; nb < 8; nb++) {
                    int col = warpN * 64 + nb * 8 + (lane & 3) * 2;
                    float o0 = lng[col]     * (acc[mi][nb][half * 2]     - mean) * inv + lnb[col];
                    float o1 = lng[col + 1] * (acc[mi][nb][half * 2 + 1] - mean) * inv + lnb[col + 1];
                    *reinterpret_cast<float2*>(C + (size_t)gr * 128 + col) = make_float2(o0, o1);
                }
            }
        }
    }
}

// ---------------- init (zero scratch) ----------------
__global__ void k_init() {
    int i = blockIdx.x * blockDim.x + threadIdx.x;
    if (i < NNEW * H_DIM) g_agg[i] = 0.f;
    if (i < NNEW) g_denom[i] = 0.f;
}

// ---------------- relation-table projections (tiny, fp32; bqr folded into wqr) ----------------
__global__ void k_rel(const float* __restrict__ rel_table,
                      const float* __restrict__ Wr,
                      const float* __restrict__ Wqr,
                      const float* __restrict__ W_ih,
                      const float* __restrict__ bqr) {
    __shared__ float sh[D_EMB];
    int r = blockIdx.x;
    int j = threadIdx.x;  // 384 threads
    if (j < D_EMB) sh[j] = rel_table[r * D_EMB + j];
    __syncthreads();
    float s = 0.f;
    const float* wrow = W_ih + j * (2 * D_EMB) + D_EMB;
    #pragma unroll 4
    for (int d = 0; d < D_EMB; d++) s = fmaf(sh[d], wrow[d], s);
    g_rel_gru[r * G3H + j] = s;
    if (j < H_DIM) {
        float s1 = 0.f, s2 = 0.f;
        #pragma unroll 4
        for (int d = 0; d < D_EMB; d++) {
            s1 = fmaf(sh[d], Wr[j * D_EMB + d], s1);
            s2 = fmaf(sh[d], Wqr[j * D_EMB + d], s2);
        }
        g_rel_wr[r * H_DIM + j] = s1;
        g_rel_wqr[r * H_DIM + j] = s2 + bqr[j];
    }
}

// ---------------- pass A: exp(logit) + denom ----------------
__global__ __launch_bounds__(256) void k_logit(
    const int* __restrict__ head, const int* __restrict__ rel,
    const int* __restrict__ qidx, const int* __restrict__ tail,
    const float* __restrict__ Wa, const float* __restrict__ ba) {
    int e = blockIdx.x * 8 + (threadIdx.x >> 5);
    if (e >= E_EDGES) return;
    int lane = threadIdx.x & 31;
    int h = head[e], rl = rel[e], qq = qidx[e];
    const float4* rw = reinterpret_cast<const float4*>(g_rel_wr) + (size_t)rl * 32;
    const float4* qw = reinterpret_cast<const float4*>(g_rel_wqr) + (size_t)qq * 32;
    float4 a = ld_half4(g_ns16 + (size_t)h * 128 + lane * 4);
    float4 b = rw[lane];
    float4 c = qw[lane];
    float4 wa = reinterpret_cast<const float4*>(Wa)[lane];
    float x0 = fmaxf(a.x + b.x + c.x, 0.f);
    float x1 = fmaxf(a.y + b.y + c.y, 0.f);
    float x2 = fmaxf(a.z + b.z + c.z, 0.f);
    float x3 = fmaxf(a.w + b.w + c.w, 0.f);
    float s = x0 * wa.x + x1 * wa.y + x2 * wa.z + x3 * wa.w;
    #pragma unroll
    for (int m = 16; m; m >>= 1) s += __shfl_xor_sync(0xffffffffu, s, m);
    if (lane == 0) {
        float ex = __expf(s + ba[0]);   // logits are O(1): exp safe without max-shift
        g_ex[e] = ex;
        atomicAdd(&g_denom[tail[e]], ex);
    }
}

// ---------------- pass C: GRU gates + weighted scatter-add ----------------
__global__ __launch_bounds__(256) void k_msg(
    const int* __restrict__ head, const int* __restrict__ rel,
    const int* __restrict__ ent, const int* __restrict__ tail,
    const float* __restrict__ bih, const float* __restrict__ bhh) {
    int e = blockIdx.x * 8 + (threadIdx.x >> 5);
    if (e >= E_EDGES) return;
    int lane = threadIdx.x & 31;
    int hd = head[e], rl = rel[e], en = ent[e], tl = tail[e];
    const __half* ep = g_ent_proj + (size_t)en * G3H;
    const __half* nh = g_node_hh + (size_t)hd * G3H;
    const float4* rg = reinterpret_cast<const float4*>(g_rel_gru) + (size_t)rl * 96;
    const float4* bi = reinterpret_cast<const float4*>(bih);
    const float4* bh = reinterpret_cast<const float4*>(bhh);

    float4 ep_r = ld_half4(ep + lane * 4);
    float4 ep_z = ld_half4(ep + 128 + lane * 4);
    float4 ep_n = ld_half4(ep + 256 + lane * 4);
    float4 nh_r = ld_half4(nh + lane * 4);
    float4 nh_z = ld_half4(nh + 128 + lane * 4);
    float4 nh_n = ld_half4(nh + 256 + lane * 4);

    float4 gr = f4add3(ep_r, rg[lane],      bi[lane]);
    float4 hr = f4add (nh_r, bh[lane]);
    float4 gz = f4add3(ep_z, rg[lane + 32], bi[lane + 32]);
    float4 hz = f4add (nh_z, bh[lane + 32]);
    float4 gn = f4add3(ep_n, rg[lane + 64], bi[lane + 64]);
    float4 hn = f4add (nh_n, bh[lane + 64]);

    float4 r4 = sig4f(f4add(gr, hr));
    float4 z4 = sig4f(f4add(gz, hz));
    float4 n4;
    n4.x = tanh_fast(gn.x + r4.x * hn.x);
    n4.y = tanh_fast(gn.y + r4.y * hn.y);
    n4.z = tanh_fast(gn.z + r4.z * hn.z);
    n4.w = tanh_fast(gn.w + r4.w * hn.w);

    float4 hs = ld_half4(g_A16 + (size_t)hd * 128 + lane * 4);
    float alpha = __fdividef(g_ex[e], g_denom[tl] + 1e-6f);

    float mx = alpha * ((1.f - z4.x) * n4.x + z4.x * hs.x);
    float my = alpha * ((1.f - z4.y) * n4.y + z4.y * hs.y);
    float mz = alpha * ((1.f - z4.z) * n4.z + z4.z * hs.z);
    float mw = alpha * ((1.f - z4.w) * n4.w + z4.w * hs.w);

    float* dst = &g_agg[(size_t)tl * H_DIM + lane * 4];
    asm volatile("red.global.add.v4.f32 [%0], {%1,%2,%3,%4};"
                 :: "l"(dst), "f"(mx), "f"(my), "f"(mz), "f"(mw) : "memory");
}

// ---------------- launcher (fork-join on two streams) ----------------
extern "C" void kernel_launch(void* const* d_in, const int* in_sizes, int n_in,
                              void* d_out, int out_size) {
    const int*   head      = (const int*)d_in[0];
    const int*   rel       = (const int*)d_in[1];
    const int*   ent       = (const int*)d_in[2];
    const int*   tail      = (const int*)d_in[3];
    const int*   qidx      = (const int*)d_in[4];
    const float* node_emb  = (const float*)d_in[5];
    const float* ent_table = (const float*)d_in[6];
    const float* rel_table = (const float*)d_in[7];
    const float* Ws        = (const float*)d_in[8];
    const float* Wr        = (const float*)d_in[9];
    const float* Wqr       = (const float*)d_in[10];
    const float* bqr       = (const float*)d_in[11];
    const float* Wa        = (const float*)d_in[12];
    const float* ba        = (const float*)d_in[13];
    const float* W_ih      = (const float*)d_in[14];
    const float* W_hh      = (const float*)d_in[15];
    const float* bih       = (const float*)d_in[16];
    const float* bhh       = (const float*)d_in[17];
    const float* Wh        = (const float*)d_in[18];
    const float* lng       = (const float*)d_in[19];
    const float* lnb       = (const float*)d_in[20];
    float* out = (float*)d_out;

    float *p_agg, *p_denom;
    __half *p_ns16, *p_node_hh, *p_ent_proj, *p_A16, *p_E16, *p_Ws16, *p_Whh16, *p_Wih16, *p_Wh16, *p_agg16;
    cudaGetSymbolAddress((void**)&p_ns16,     g_ns16);
    cudaGetSymbolAddress((void**)&p_node_hh,  g_node_hh);
    cudaGetSymbolAddress((void**)&p_ent_proj, g_ent_proj);
    cudaGetSymbolAddress((void**)&p_agg,      g_agg);
    cudaGetSymbolAddress((void**)&p_denom,    g_denom);
    cudaGetSymbolAddress((void**)&p_agg16,    g_agg16);
    cudaGetSymbolAddress((void**)&p_A16,   g_A16);
    cudaGetSymbolAddress((void**)&p_E16,   g_E16);
    cudaGetSymbolAddress((void**)&p_Ws16,  g_Ws16);
    cudaGetSymbolAddress((void**)&p_Whh16, g_Whh16);
    cudaGetSymbolAddress((void**)&p_Wih16, g_Wih16);
    cudaGetSymbolAddress((void**)&p_Wh16,  g_Wh16);

    cudaFuncSetAttribute(k_hmma16_nt<1>, cudaFuncAttributeMaxDynamicSharedMemorySize, HM16_SMEM);
    cudaFuncSetAttribute(k_hmma16_nt<3>, cudaFuncAttributeMaxDynamicSharedMemorySize, HM16_SMEM);
    cudaFuncSetAttribute(k_out16, cudaFuncAttributeMaxDynamicSharedMemorySize, HM16_SMEM);

    // ---- fork: s2 branches off the main (legacy) stream ----
    cudaEventRecord(g_evFork, 0);
    cudaStreamWaitEvent(g_s2, g_evFork, 0);

    // ---- chain B (s2): independent conversions ----
    k_cvt16<<<(NENT * 32 + 255) / 256, 256, 0, g_s2>>>(ent_table, D_EMB, D_EMB, p_E16, NENT);
    k_cvt16<<<(G3H * 32 + 255) / 256, 256, 0, g_s2>>>(W_hh, H_DIM, H_DIM,     p_Whh16, G3H);
    k_cvt16<<<(G3H * 32 + 255) / 256, 256, 0, g_s2>>>(W_ih, D_EMB, 2 * D_EMB, p_Wih16, G3H);
    k_cvt16<<<(128 * 32 + 255) / 256, 256, 0, g_s2>>>(Wh, H_DIM, H_DIM, p_Wh16, 128);

    // ---- chain A (s0): init, rel, A16/Ws16 cvts, ns16 GEMM, logit ----
    k_init<<<(NNEW * H_DIM + 255) / 256, 256>>>();
    k_rel<<<NREL, G3H>>>(rel_table, Wr, Wqr, W_ih, bqr);
    k_cvt16<<<(NOLD * 32 + 255) / 256, 256>>>(node_emb, H_DIM, H_DIM, p_A16, NOLD);
    cudaEventRecord(g_evA, 0);                       // A16 ready for chain B's node_hh GEMM
    k_cvt16<<<(128 * 32 + 255) / 256, 256>>>(Ws, H_DIM, H_DIM, p_Ws16, 128);
    {
        int grid = (NOLD + 127) / 128;
        k_hmma16_nt<1><<<grid, 256, HM16_SMEM>>>(p_A16, p_Ws16, p_ns16, NOLD);
    }
    k_logit<<<E_EDGES / 8, 256>>>(head, rel, qidx, tail, Wa, ba);

    // ---- chain B (s2): gate GEMMs (node_hh needs A16) ----
    cudaStreamWaitEvent(g_s2, g_evA, 0);
    {
        int grid = (NOLD + 127) / 128;
        k_hmma16_nt<3><<<grid, 256, HM16_SMEM, g_s2>>>(p_A16, p_Whh16, p_node_hh, NOLD);
        int gride = (NENT + 127) / 128;
        k_hmma16_nt<3><<<gride, 256, HM16_SMEM, g_s2>>>(p_E16, p_Wih16, p_ent_proj, NENT);
    }
    cudaEventRecord(g_evJ, g_s2);

    // ---- join: k_msg needs both chains ----
    cudaStreamWaitEvent(0, g_evJ, 0);
    k_msg<<<E_EDGES / 8, 256>>>(head, rel, ent, tail, bih, bhh);
    // out: agg -> fp16 plane, HMMA GEMM + relu + LayerNorm
    k_cvt16<<<(NNEW * 32 + 255) / 256, 256>>>(p_agg, H_DIM, H_DIM, p_agg16, NNEW);
    k_out16<<<(NNEW + 127) / 128, 256, HM16_SMEM>>>(p_agg16, p_Wh16, lng, lnb, out, NNEW);
}